// round 1
// baseline (speedup 1.0000x reference)
#include <cuda_runtime.h>
#include <math.h>

#define B_TOT 512
#define SEQ   392
#define CH    128
#define NHEAD 4
#define HD    32
#define NWIN  128
#define MROWS (B_TOT*SEQ)          // 200704
#define NN    (SEQ*SEQ)            // 153664
#define QKV_SCALE 0.17677669529663687f  // 32^-0.5
#define KTS   401                  // padded stride for transposed K in smem

// -------- scratch (device globals: no allocations allowed) --------
__device__ float g_q[(size_t)B_TOT*NHEAD*SEQ*HD];
__device__ float g_k[(size_t)B_TOT*NHEAD*SEQ*HD];
__device__ float g_v[(size_t)B_TOT*NHEAD*SEQ*HD];
__device__ float g_ao[(size_t)MROWS*CH];
__device__ float g_bias[(size_t)NHEAD*NN];

// ============================================================
// Kernel 0: gather relative-position bias  bias[h][n][m]
// ============================================================
__global__ void bias_gather_kernel(const float* __restrict__ table,
                                   const int* __restrict__ ridx) {
    int t = blockIdx.x * 256 + threadIdx.x;
    if (t >= NN) return;
    int r = ridx[t];
#pragma unroll
    for (int h = 0; h < NHEAD; h++)
        g_bias[h * NN + t] = table[r * NHEAD + h];
}

// ============================================================
// GEMM: Y[M, NCOLS] = X[M,128] @ W[NCOLS,128]^T
// MODE 0: X = x input, scatter into g_q (scaled) / g_k / g_v
// MODE 1: X = g_ao,    Y = out + proj_b
// block tile 64x64, 256 threads, 4x4 microtile
// ============================================================
template <int MODE>
__global__ void __launch_bounds__(256) gemm64(const float* __restrict__ Xin,
                                              const float* __restrict__ W,
                                              const float* __restrict__ bias,
                                              float* __restrict__ out) {
    __shared__ float Xs[64][16];
    __shared__ float Ws[16][64];
    const float* X = (MODE == 0) ? Xin : g_ao;

    int m0 = blockIdx.x * 64, n0 = blockIdx.y * 64;
    int tid = threadIdx.x;
    int tx = tid & 15, ty = tid >> 4;
    int lrow = tid >> 2, lcg = tid & 3;

    float acc[4][4] = {};

    for (int k0 = 0; k0 < CH; k0 += 16) {
        float4 xa = *(const float4*)(X + (size_t)(m0 + lrow) * CH + k0 + lcg * 4);
        float4 wa = *(const float4*)(W + (size_t)(n0 + lrow) * CH + k0 + lcg * 4);
        __syncthreads();
        *(float4*)&Xs[lrow][lcg * 4] = xa;
        Ws[lcg * 4 + 0][lrow] = wa.x;
        Ws[lcg * 4 + 1][lrow] = wa.y;
        Ws[lcg * 4 + 2][lrow] = wa.z;
        Ws[lcg * 4 + 3][lrow] = wa.w;
        __syncthreads();
#pragma unroll
        for (int k = 0; k < 16; k++) {
            float a0 = Xs[ty * 4 + 0][k];
            float a1 = Xs[ty * 4 + 1][k];
            float a2 = Xs[ty * 4 + 2][k];
            float a3 = Xs[ty * 4 + 3][k];
            float4 bb = *(const float4*)&Ws[k][tx * 4];
            acc[0][0] = fmaf(a0, bb.x, acc[0][0]);
            acc[0][1] = fmaf(a0, bb.y, acc[0][1]);
            acc[0][2] = fmaf(a0, bb.z, acc[0][2]);
            acc[0][3] = fmaf(a0, bb.w, acc[0][3]);
            acc[1][0] = fmaf(a1, bb.x, acc[1][0]);
            acc[1][1] = fmaf(a1, bb.y, acc[1][1]);
            acc[1][2] = fmaf(a1, bb.z, acc[1][2]);
            acc[1][3] = fmaf(a1, bb.w, acc[1][3]);
            acc[2][0] = fmaf(a2, bb.x, acc[2][0]);
            acc[2][1] = fmaf(a2, bb.y, acc[2][1]);
            acc[2][2] = fmaf(a2, bb.z, acc[2][2]);
            acc[2][3] = fmaf(a2, bb.w, acc[2][3]);
            acc[3][0] = fmaf(a3, bb.x, acc[3][0]);
            acc[3][1] = fmaf(a3, bb.y, acc[3][1]);
            acc[3][2] = fmaf(a3, bb.z, acc[3][2]);
            acc[3][3] = fmaf(a3, bb.w, acc[3][3]);
        }
    }

    if (MODE == 0) {
        int seg = n0 >> 7;  // whole 64-wide tile lies inside one qkv segment
        float* dst = (seg == 0) ? g_q : (seg == 1) ? g_k : g_v;
        float sc = (seg == 0) ? QKV_SCALE : 1.0f;
        int jbase = (n0 & 127) + tx * 4;
#pragma unroll
        for (int i = 0; i < 4; i++) {
            int m = m0 + ty * 4 + i;
            int b = m / SEQ, n = m % SEQ;
#pragma unroll
            for (int j = 0; j < 4; j++) {
                int jj = jbase + j;
                int h = jj >> 5, d = jj & 31;
                dst[(((b * NHEAD + h) * SEQ) + n) * HD + d] = acc[i][j] * sc;
            }
        }
    } else {
        float4 pb = *(const float4*)(bias + n0 + tx * 4);
#pragma unroll
        for (int i = 0; i < 4; i++) {
            int m = m0 + ty * 4 + i;
            float4 o;
            o.x = acc[i][0] + pb.x;
            o.y = acc[i][1] + pb.y;
            o.z = acc[i][2] + pb.z;
            o.w = acc[i][3] + pb.w;
            *(float4*)(out + (size_t)m * CH + n0 + tx * 4) = o;
        }
    }
}

// ============================================================
// Attention: one CTA per (b, h). K^T and V in SMEM, exact
// softmax per 32-row tile, then block-cooperative P @ V.
// Block order groups blocks sharing the same window -> mask
// slice stays L2-resident.
// ============================================================
__global__ void __launch_bounds__(256, 1) attn_kernel(const float* __restrict__ mask) {
    extern __shared__ float sm[];
    float* Kt = sm;                       // 32 * KTS
    float* Vb = sm + 32 * KTS;            // SEQ * HD
    float* Pb = Vb + SEQ * HD;            // 32 * SEQ

    int g = blockIdx.x;
    int w = g >> 4;
    int r = g & 15;
    int b = (r >> 2) * NWIN + w;
    int h = r & 3;
    int base = ((b * NHEAD + h) * SEQ) * HD;

    int tid = threadIdx.x;
    // ---- load K transposed (conflict-free via odd stride) and V ----
    for (int i = tid; i < SEQ * HD; i += 256) {
        int m = i >> 5, d = i & 31;
        Kt[d * KTS + m] = g_k[base + i];
        Vb[i] = g_v[base + i];
    }
    __syncthreads();

    int lane = tid & 31, warp = tid >> 5;
    const float* biasp = g_bias + h * NN;
    const float* maskp = mask + w * NN;
    int ty = tid >> 3, tx = tid & 7;

    for (int t = 0; t < 13; t++) {
        int r0 = t * 32;
        float acc[4][13];
        float qreg[4];
        bool rv[4];

        // ---- init: bias + mask (coalesced LDG, high MLP) ----
#pragma unroll
        for (int j = 0; j < 4; j++) {
            int row = r0 + warp * 4 + j;
            rv[j] = row < SEQ;
            qreg[j] = rv[j] ? g_q[base + row * HD + lane] : 0.0f;
            const float* brow = biasp + (size_t)row * SEQ;
            const float* mrow = maskp + (size_t)row * SEQ;
#pragma unroll
            for (int i = 0; i < 13; i++) {
                int m = i * 32 + lane;
                acc[j][i] = (rv[j] && m < SEQ) ? (brow[m] + mrow[m]) : -INFINITY;
            }
        }

        // ---- scores: acc += q . k ----
#pragma unroll 8
        for (int d = 0; d < HD; d++) {
            float q0 = __shfl_sync(0xffffffffu, qreg[0], d);
            float q1 = __shfl_sync(0xffffffffu, qreg[1], d);
            float q2 = __shfl_sync(0xffffffffu, qreg[2], d);
            float q3 = __shfl_sync(0xffffffffu, qreg[3], d);
            const float* ktr = Kt + d * KTS;
#pragma unroll
            for (int i = 0; i < 13; i++) {
                float kv = (i < 12 || lane < 8) ? ktr[i * 32 + lane] : 0.0f;
                acc[0][i] = fmaf(q0, kv, acc[0][i]);
                acc[1][i] = fmaf(q1, kv, acc[1][i]);
                acc[2][i] = fmaf(q2, kv, acc[2][i]);
                acc[3][i] = fmaf(q3, kv, acc[3][i]);
            }
        }

        // ---- softmax per row, write P to smem ----
#pragma unroll
        for (int j = 0; j < 4; j++) {
            if (!rv[j]) continue;  // uniform per warp
            float mx = acc[j][0];
#pragma unroll
            for (int i = 1; i < 13; i++) mx = fmaxf(mx, acc[j][i]);
#pragma unroll
            for (int o = 16; o; o >>= 1)
                mx = fmaxf(mx, __shfl_xor_sync(0xffffffffu, mx, o));
            float s = 0.0f;
#pragma unroll
            for (int i = 0; i < 13; i++) {
                float e = __expf(acc[j][i] - mx);
                acc[j][i] = e;
                s += e;
            }
#pragma unroll
            for (int o = 16; o; o >>= 1)
                s += __shfl_xor_sync(0xffffffffu, s, o);
            float inv = __frcp_rn(s);
            float* prow = Pb + (warp * 4 + j) * SEQ;
#pragma unroll
            for (int i = 0; i < 13; i++) {
                if (i < 12 || lane < 8) prow[i * 32 + lane] = acc[j][i] * inv;
            }
        }
        __syncthreads();

        // ---- P @ V : each thread = 1 row x 4 cols, m unrolled by 4 ----
        int orow = r0 + ty;
        if (orow < SEQ) {
            float4 o = make_float4(0.f, 0.f, 0.f, 0.f);
            const float* prow = Pb + ty * SEQ;
#pragma unroll 2
            for (int m = 0; m < SEQ; m += 4) {
                float4 pv = *(const float4*)(prow + m);
                const float* v0 = Vb + m * HD + tx * 4;
                float4 va = *(const float4*)(v0);
                float4 vb = *(const float4*)(v0 + HD);
                float4 vc = *(const float4*)(v0 + 2 * HD);
                float4 vd = *(const float4*)(v0 + 3 * HD);
                o.x = fmaf(pv.x, va.x, o.x); o.y = fmaf(pv.x, va.y, o.y);
                o.z = fmaf(pv.x, va.z, o.z); o.w = fmaf(pv.x, va.w, o.w);
                o.x = fmaf(pv.y, vb.x, o.x); o.y = fmaf(pv.y, vb.y, o.y);
                o.z = fmaf(pv.y, vb.z, o.z); o.w = fmaf(pv.y, vb.w, o.w);
                o.x = fmaf(pv.z, vc.x, o.x); o.y = fmaf(pv.z, vc.y, o.y);
                o.z = fmaf(pv.z, vc.z, o.z); o.w = fmaf(pv.z, vc.w, o.w);
                o.x = fmaf(pv.w, vd.x, o.x); o.y = fmaf(pv.w, vd.y, o.y);
                o.z = fmaf(pv.w, vd.z, o.z); o.w = fmaf(pv.w, vd.w, o.w);
            }
            *(float4*)(g_ao + ((size_t)b * SEQ + orow) * CH + h * HD + tx * 4) = o;
        }
        __syncthreads();
    }
}

// ============================================================
extern "C" void kernel_launch(void* const* d_in, const int* in_sizes, int n_in,
                              void* d_out, int out_size) {
    (void)in_sizes; (void)n_in; (void)out_size;
    const float* x          = (const float*)d_in[0];
    const float* mask       = (const float*)d_in[1];
    const float* qkv_w      = (const float*)d_in[2];
    const float* proj_w     = (const float*)d_in[3];
    const float* proj_b     = (const float*)d_in[4];
    const float* bias_table = (const float*)d_in[5];
    const int*   rel_index  = (const int*)d_in[6];
    float* out = (float*)d_out;

    size_t smem = (size_t)(32 * KTS + SEQ * HD + 32 * SEQ) * sizeof(float);
    cudaFuncSetAttribute(attn_kernel, cudaFuncAttributeMaxDynamicSharedMemorySize,
                         (int)smem);

    bias_gather_kernel<<<(NN + 255) / 256, 256>>>(bias_table, rel_index);
    gemm64<0><<<dim3(MROWS / 64, 384 / 64), 256>>>(x, qkv_w, nullptr, nullptr);
    attn_kernel<<<B_TOT * NHEAD, 256, smem>>>(mask);
    gemm64<1><<<dim3(MROWS / 64, CH / 64), 256>>>(nullptr, proj_w, proj_b, out);
}

// round 3
// speedup vs baseline: 1.3106x; 1.3106x over previous
#include <cuda_runtime.h>
#include <cstdint>
#include <math.h>

#define B_TOT 512
#define SEQ   392
#define CH    128
#define NHEAD 4
#define HD    32
#define NWIN  128
#define MROWS (B_TOT*SEQ)          // 200704
#define NN    (SEQ*SEQ)            // 153664
#define QKV_SCALE 0.17677669529663687f

#define QSTR  36                   // smem row stride (floats) -> conflict-free frags
#define NT    49                   // 392/8 n-tiles
#define MT    25                   // ceil(392/16) m-tiles

// -------- scratch (device globals: no allocations allowed) --------
__device__ float g_q[(size_t)B_TOT*NHEAD*SEQ*HD];
__device__ float g_k[(size_t)B_TOT*NHEAD*SEQ*HD];
__device__ float g_v[(size_t)B_TOT*NHEAD*SEQ*HD];
__device__ float g_ao[(size_t)MROWS*CH];
__device__ float g_bias[(size_t)NHEAD*NN];    // [h][row_q][col_k]

// ============================================================
__device__ __forceinline__ uint32_t f2tf32(float x) {
    uint32_t r;
    asm("cvt.rna.tf32.f32 %0, %1;" : "=r"(r) : "f"(x));
    return r;
}
__device__ __forceinline__ void mma_tf32(float& d0, float& d1, float& d2, float& d3,
                                         uint32_t a0, uint32_t a1, uint32_t a2, uint32_t a3,
                                         uint32_t b0, uint32_t b1) {
    asm volatile("mma.sync.aligned.m16n8k8.row.col.f32.tf32.tf32.f32 "
                 "{%0,%1,%2,%3}, {%4,%5,%6,%7}, {%8,%9}, {%0,%1,%2,%3};"
                 : "+f"(d0), "+f"(d1), "+f"(d2), "+f"(d3)
                 : "r"(a0), "r"(a1), "r"(a2), "r"(a3), "r"(b0), "r"(b1));
}

// ============================================================
// Prep: bias[h][n][m] = table[ridx[n][m]][h]
// ============================================================
__global__ void bias_gather_kernel(const float* __restrict__ table,
                                   const int* __restrict__ ridx) {
    int t = blockIdx.x * 256 + threadIdx.x;
    if (t >= NN) return;
    int r = ridx[t];
    float4 tv = *(const float4*)(table + (size_t)r * 4);
    g_bias[0 * (size_t)NN + t] = tv.x;
    g_bias[1 * (size_t)NN + t] = tv.y;
    g_bias[2 * (size_t)NN + t] = tv.z;
    g_bias[3 * (size_t)NN + t] = tv.w;
}

// ============================================================
// GEMM: Y[M, NCOLS] = X[M,128] @ W[NCOLS,128]^T  (fp32, at FMA roofline)
// ============================================================
template <int MODE>
__global__ void __launch_bounds__(256) gemm64(const float* __restrict__ Xin,
                                              const float* __restrict__ W,
                                              const float* __restrict__ bias,
                                              float* __restrict__ out) {
    __shared__ float Xs[64][16];
    __shared__ float Ws[16][64];
    const float* X = (MODE == 0) ? Xin : g_ao;

    int m0 = blockIdx.x * 64, n0 = blockIdx.y * 64;
    int tid = threadIdx.x;
    int tx = tid & 15, ty = tid >> 4;
    int lrow = tid >> 2, lcg = tid & 3;
    float acc[4][4] = {};

    for (int k0 = 0; k0 < CH; k0 += 16) {
        float4 xa = *(const float4*)(X + (size_t)(m0 + lrow) * CH + k0 + lcg * 4);
        float4 wa = *(const float4*)(W + (size_t)(n0 + lrow) * CH + k0 + lcg * 4);
        __syncthreads();
        *(float4*)&Xs[lrow][lcg * 4] = xa;
        Ws[lcg * 4 + 0][lrow] = wa.x;
        Ws[lcg * 4 + 1][lrow] = wa.y;
        Ws[lcg * 4 + 2][lrow] = wa.z;
        Ws[lcg * 4 + 3][lrow] = wa.w;
        __syncthreads();
#pragma unroll
        for (int k = 0; k < 16; k++) {
            float a0 = Xs[ty * 4 + 0][k], a1 = Xs[ty * 4 + 1][k];
            float a2 = Xs[ty * 4 + 2][k], a3 = Xs[ty * 4 + 3][k];
            float4 bb = *(const float4*)&Ws[k][tx * 4];
            acc[0][0] = fmaf(a0, bb.x, acc[0][0]); acc[0][1] = fmaf(a0, bb.y, acc[0][1]);
            acc[0][2] = fmaf(a0, bb.z, acc[0][2]); acc[0][3] = fmaf(a0, bb.w, acc[0][3]);
            acc[1][0] = fmaf(a1, bb.x, acc[1][0]); acc[1][1] = fmaf(a1, bb.y, acc[1][1]);
            acc[1][2] = fmaf(a1, bb.z, acc[1][2]); acc[1][3] = fmaf(a1, bb.w, acc[1][3]);
            acc[2][0] = fmaf(a2, bb.x, acc[2][0]); acc[2][1] = fmaf(a2, bb.y, acc[2][1]);
            acc[2][2] = fmaf(a2, bb.z, acc[2][2]); acc[2][3] = fmaf(a2, bb.w, acc[2][3]);
            acc[3][0] = fmaf(a3, bb.x, acc[3][0]); acc[3][1] = fmaf(a3, bb.y, acc[3][1]);
            acc[3][2] = fmaf(a3, bb.z, acc[3][2]); acc[3][3] = fmaf(a3, bb.w, acc[3][3]);
        }
    }

    if (MODE == 0) {
        int seg = n0 >> 7;
        float* dst = (seg == 0) ? g_q : (seg == 1) ? g_k : g_v;
        float sc = (seg == 0) ? QKV_SCALE : 1.0f;
        int jbase = (n0 & 127) + tx * 4;
#pragma unroll
        for (int i = 0; i < 4; i++) {
            int m = m0 + ty * 4 + i;
            int b = m / SEQ, n = m % SEQ;
#pragma unroll
            for (int j = 0; j < 4; j++) {
                int jj = jbase + j;
                int h = jj >> 5, d = jj & 31;
                dst[((size_t)((b * NHEAD + h) * SEQ) + n) * HD + d] = acc[i][j] * sc;
            }
        }
    } else {
        float4 pb = *(const float4*)(bias + n0 + tx * 4);
#pragma unroll
        for (int i = 0; i < 4; i++) {
            int m = m0 + ty * 4 + i;
            float4 o;
            o.x = acc[i][0] + pb.x; o.y = acc[i][1] + pb.y;
            o.z = acc[i][2] + pb.z; o.w = acc[i][3] + pb.w;
            *(float4*)(out + (size_t)m * CH + n0 + tx * 4) = o;
        }
    }
}

// ============================================================
// Attention via mma.sync tf32: one CTA per (b, h), 8 warps.
// ============================================================
#define Q_ELE (400*QSTR)
#define K_ELE (392*QSTR)
#define SMEM_FLOATS (Q_ELE + 2*K_ELE + 8*128)

__global__ void __launch_bounds__(256, 1) attn_mma(const float* __restrict__ mask) {
    extern __shared__ float sm[];
    float* Qs = sm;
    float* Ks = sm + Q_ELE;
    float* Vs = Ks + K_ELE;
    float* Ps = Vs + K_ELE;

    int g = blockIdx.x;
    int w = g >> 4;
    int r = g & 15;
    int b = (r >> 2) * NWIN + w;
    int h = r & 3;
    size_t base = ((size_t)(b * NHEAD + h) * SEQ) * HD;

    int tid = threadIdx.x;
    // ---- stage Q/K/V (tf32-rounded), float4 per thread ----
    for (int s = tid; s < SEQ * 8; s += 256) {
        int row = s >> 3, c = s & 7;
        float4 q = *(const float4*)(g_q + base + (size_t)row * HD + c * 4);
        float4 k = *(const float4*)(g_k + base + (size_t)row * HD + c * 4);
        float4 v = *(const float4*)(g_v + base + (size_t)row * HD + c * 4);
        uint4 qt = make_uint4(f2tf32(q.x), f2tf32(q.y), f2tf32(q.z), f2tf32(q.w));
        uint4 kt = make_uint4(f2tf32(k.x), f2tf32(k.y), f2tf32(k.z), f2tf32(k.w));
        uint4 vt = make_uint4(f2tf32(v.x), f2tf32(v.y), f2tf32(v.z), f2tf32(v.w));
        int o = row * QSTR + c * 4;
        *(uint4*)(Qs + o) = qt;
        *(uint4*)(Ks + o) = kt;
        *(uint4*)(Vs + o) = vt;
    }
    for (int s = tid; s < 8 * QSTR; s += 256) Qs[392 * QSTR + s] = 0.0f;  // pad rows
    __syncthreads();

    int lane = tid & 31, warp = tid >> 5;
    int grp = lane >> 2, q4 = lane & 3;
    float* Pw = Ps + warp * 128;   // 16x8 bounce buffer

    const float* biasp = g_bias + (size_t)h * NN;
    const float* maskp = mask + (size_t)w * NN;

    for (int mt = warp; mt < MT; mt += 8) {
        int m0 = mt * 16;
        int row0 = m0 + grp, row1 = m0 + grp + 8;
        int r0c = (row0 < SEQ) ? row0 : SEQ - 1;
        int r1c = (row1 < SEQ) ? row1 : SEQ - 1;
        const float* b0p = biasp + (size_t)r0c * SEQ + 2 * q4;
        const float* b1p = biasp + (size_t)r1c * SEQ + 2 * q4;
        const float* m0p = maskp + (size_t)r0c * SEQ + 2 * q4;
        const float* m1p = maskp + (size_t)r1c * SEQ + 2 * q4;

        // A fragments of Q (k = 0..31 in 4 steps of 8)
        uint32_t aq[4][4];
#pragma unroll
        for (int ks = 0; ks < 4; ks++) {
            const uint32_t* q0 = (const uint32_t*)(Qs + row0 * QSTR + ks * 8 + q4);
            const uint32_t* q1 = (const uint32_t*)(Qs + row1 * QSTR + ks * 8 + q4);
            aq[ks][0] = q0[0];
            aq[ks][1] = q1[0];
            aq[ks][2] = q0[4];
            aq[ks][3] = q1[4];
        }

        float oacc[4][4] = {};
        float rs0 = 0.0f, rs1 = 0.0f;

        for (int nt = 0; nt < NT; nt++) {
            int n0 = nt * 8;
            float2 bb0 = *(const float2*)(b0p + n0);
            float2 bb1 = *(const float2*)(b1p + n0);
            float2 mm0 = *(const float2*)(m0p + n0);
            float2 mm1 = *(const float2*)(m1p + n0);
            float c0 = bb0.x + mm0.x, c1 = bb0.y + mm0.y;
            float c2 = bb1.x + mm1.x, c3 = bb1.y + mm1.y;

            // ---- S tile: Q(16x32) @ K^T(32x8) ----
#pragma unroll
            for (int ks = 0; ks < 4; ks++) {
                const uint32_t* kp = (const uint32_t*)(Ks + (n0 + grp) * QSTR + ks * 8 + q4);
                mma_tf32(c0, c1, c2, c3,
                         aq[ks][0], aq[ks][1], aq[ks][2], aq[ks][3],
                         kp[0], kp[4]);
            }

            // ---- unnormalized softmax ----
            float e0 = __expf(c0), e1 = __expf(c1);
            float e2 = __expf(c2), e3 = __expf(c3);
            rs0 += e0 + e1;
            rs1 += e2 + e3;

            // ---- relayout P: C-frag -> A-frag through smem ----
            Pw[grp * 8 + 2 * q4]       = __uint_as_float(f2tf32(e0));
            Pw[grp * 8 + 2 * q4 + 1]   = __uint_as_float(f2tf32(e1));
            Pw[(grp + 8) * 8 + 2 * q4]     = __uint_as_float(f2tf32(e2));
            Pw[(grp + 8) * 8 + 2 * q4 + 1] = __uint_as_float(f2tf32(e3));
            __syncwarp();
            uint32_t ap0 = *(const uint32_t*)(Pw + grp * 8 + q4);
            uint32_t ap1 = *(const uint32_t*)(Pw + (grp + 8) * 8 + q4);
            uint32_t ap2 = *(const uint32_t*)(Pw + grp * 8 + q4 + 4);
            uint32_t ap3 = *(const uint32_t*)(Pw + (grp + 8) * 8 + q4 + 4);
            __syncwarp();

            // ---- O(16x32) += P(16x8) @ V(8x32) ----
#pragma unroll
            for (int j = 0; j < 4; j++) {
                const uint32_t* vp0 = (const uint32_t*)(Vs + (n0 + q4) * QSTR + j * 8 + grp);
                const uint32_t* vp1 = (const uint32_t*)(Vs + (n0 + q4 + 4) * QSTR + j * 8 + grp);
                mma_tf32(oacc[j][0], oacc[j][1], oacc[j][2], oacc[j][3],
                         ap0, ap1, ap2, ap3, vp0[0], vp1[0]);
            }
        }

        // ---- rowsum across the quad, normalize, store ----
        rs0 += __shfl_xor_sync(0xffffffffu, rs0, 1);
        rs0 += __shfl_xor_sync(0xffffffffu, rs0, 2);
        rs1 += __shfl_xor_sync(0xffffffffu, rs1, 1);
        rs1 += __shfl_xor_sync(0xffffffffu, rs1, 2);
        float inv0 = __frcp_rn(rs0), inv1 = __frcp_rn(rs1);

        if (row0 < SEQ) {
            float* op = g_ao + ((size_t)b * SEQ + row0) * CH + h * HD + 2 * q4;
#pragma unroll
            for (int j = 0; j < 4; j++) {
                float2 o = make_float2(oacc[j][0] * inv0, oacc[j][1] * inv0);
                *(float2*)(op + j * 8) = o;
            }
        }
        if (row1 < SEQ) {
            float* op = g_ao + ((size_t)b * SEQ + row1) * CH + h * HD + 2 * q4;
#pragma unroll
            for (int j = 0; j < 4; j++) {
                float2 o = make_float2(oacc[j][2] * inv1, oacc[j][3] * inv1);
                *(float2*)(op + j * 8) = o;
            }
        }
    }
}

// ============================================================
extern "C" void kernel_launch(void* const* d_in, const int* in_sizes, int n_in,
                              void* d_out, int out_size) {
    (void)in_sizes; (void)n_in; (void)out_size;
    const float* x          = (const float*)d_in[0];
    const float* mask       = (const float*)d_in[1];
    const float* qkv_w      = (const float*)d_in[2];
    const float* proj_w     = (const float*)d_in[3];
    const float* proj_b     = (const float*)d_in[4];
    const float* bias_table = (const float*)d_in[5];
    const int*   rel_index  = (const int*)d_in[6];
    float* out = (float*)d_out;

    size_t smem = (size_t)SMEM_FLOATS * sizeof(float);
    cudaFuncSetAttribute(attn_mma, cudaFuncAttributeMaxDynamicSharedMemorySize, (int)smem);

    bias_gather_kernel<<<(NN + 255) / 256, 256>>>(bias_table, rel_index);
    gemm64<0><<<dim3(MROWS / 64, 384 / 64), 256>>>(x, qkv_w, nullptr, nullptr);
    attn_mma<<<B_TOT * NHEAD, 256, smem>>>(mask);
    gemm64<1><<<dim3(MROWS / 64, CH / 64), 256>>>(nullptr, proj_w, proj_b, out);
}

// round 4
// speedup vs baseline: 3.2331x; 2.4669x over previous
#include <cuda_runtime.h>
#include <cstdint>
#include <math.h>

#define B_TOT 512
#define SEQ   392
#define CH    128
#define NHEAD 4
#define HD    32
#define NWIN  128
#define MROWS (B_TOT*SEQ)          // 200704
#define NN    (SEQ*SEQ)            // 153664
#define QKV_SCALE 0.17677669529663687f

#define KVSTR 36                   // smem row stride -> conflict-free fragments
#define NT    49                   // 392/8 n-tiles
#define MT    25                   // ceil(392/16) m-tiles

// -------- scratch (device globals: no allocations allowed) --------
__device__ float g_q[(size_t)B_TOT*NHEAD*SEQ*HD];
__device__ float g_k[(size_t)B_TOT*NHEAD*SEQ*HD];
__device__ float g_v[(size_t)B_TOT*NHEAD*SEQ*HD];
__device__ float g_ao[(size_t)MROWS*CH];
__device__ float g_bias[(size_t)NHEAD*NN];    // [h][row_q][col_k]
__device__ int   g_mflag[NWIN];

// ============================================================
__device__ __forceinline__ uint32_t f2tf32(float x) {
    uint32_t r;
    asm("cvt.rna.tf32.f32 %0, %1;" : "=r"(r) : "f"(x));
    return r;
}
__device__ __forceinline__ void mma_tf32(float& d0, float& d1, float& d2, float& d3,
                                         uint32_t a0, uint32_t a1, uint32_t a2, uint32_t a3,
                                         uint32_t b0, uint32_t b1) {
    asm volatile("mma.sync.aligned.m16n8k8.row.col.f32.tf32.tf32.f32 "
                 "{%0,%1,%2,%3}, {%4,%5,%6,%7}, {%8,%9}, {%0,%1,%2,%3};"
                 : "+f"(d0), "+f"(d1), "+f"(d2), "+f"(d3)
                 : "r"(a0), "r"(a1), "r"(a2), "r"(a3), "r"(b0), "r"(b1));
}

// ============================================================
// Prep: bias[h][n][m] = table[ridx[n][m]][h]
// ============================================================
__global__ void bias_gather_kernel(const float* __restrict__ table,
                                   const int* __restrict__ ridx) {
    int t = blockIdx.x * 256 + threadIdx.x;
    if (t >= NN) return;
    int r = ridx[t];
    float4 tv = *(const float4*)(table + (size_t)r * 4);
    g_bias[0 * (size_t)NN + t] = tv.x;
    g_bias[1 * (size_t)NN + t] = tv.y;
    g_bias[2 * (size_t)NN + t] = tv.z;
    g_bias[3 * (size_t)NN + t] = tv.w;
}

// ============================================================
// Prep: per-window "mask is nonzero" flag
// ============================================================
__global__ void maskflag_kernel(const float* __restrict__ mask) {
    int w = blockIdx.x;
    const float* mp = mask + (size_t)w * NN;
    int any = 0;
    for (int i = threadIdx.x; i < NN; i += 256)
        any |= (mp[i] != 0.0f);
    any = __syncthreads_or(any);
    if (threadIdx.x == 0) g_mflag[w] = any;
}

// ============================================================
// tf32 tensor-core GEMM: Y[M,N] = X[M,128] @ W[N,128]^T
// CTA 64x64, 8 warps (4x2), warp tile 16x32.
// MODE 0: X = x, scatter into g_q (scaled) / g_k / g_v
// MODE 1: X = g_ao, Y = out + proj_b
// ============================================================
template <int MODE>
__global__ void __launch_bounds__(256) gemm_tc(const float* __restrict__ Xin,
                                               const float* __restrict__ W,
                                               const float* __restrict__ bias,
                                               float* __restrict__ out) {
    __shared__ float Xs[64 * KVSTR];
    __shared__ float Ws[64 * KVSTR];
    const float* X = (MODE == 0) ? Xin : g_ao;

    int m0 = blockIdx.x * 64;
    int n0 = blockIdx.y * 64;
    int tid = threadIdx.x;
    int lane = tid & 31, warp = tid >> 5;
    int wm = warp >> 1, wn = warp & 1;
    int grp = lane >> 2, q4 = lane & 3;

    float acc[4][4] = {};   // [n-frag j][c0..c3]

    for (int k0 = 0; k0 < CH; k0 += 32) {
        __syncthreads();
#pragma unroll
        for (int it = 0; it < 2; it++) {
            int s = tid + it * 256;
            int row = s >> 3, c = s & 7;
            float4 xv = *(const float4*)(X + (size_t)(m0 + row) * CH + k0 + c * 4);
            float4 wv = *(const float4*)(W + (size_t)(n0 + row) * CH + k0 + c * 4);
            uint4 xt = make_uint4(f2tf32(xv.x), f2tf32(xv.y), f2tf32(xv.z), f2tf32(xv.w));
            uint4 wt = make_uint4(f2tf32(wv.x), f2tf32(wv.y), f2tf32(wv.z), f2tf32(wv.w));
            *(uint4*)(Xs + row * KVSTR + c * 4) = xt;
            *(uint4*)(Ws + row * KVSTR + c * 4) = wt;
        }
        __syncthreads();
#pragma unroll
        for (int ks = 0; ks < 4; ks++) {
            const uint32_t* xp0 = (const uint32_t*)(Xs + (wm * 16 + grp) * KVSTR + ks * 8 + q4);
            const uint32_t* xp1 = (const uint32_t*)(Xs + (wm * 16 + grp + 8) * KVSTR + ks * 8 + q4);
            uint32_t a0 = xp0[0], a1 = xp1[0], a2 = xp0[4], a3 = xp1[4];
#pragma unroll
            for (int j = 0; j < 4; j++) {
                const uint32_t* wp = (const uint32_t*)(Ws + (wn * 32 + j * 8 + grp) * KVSTR + ks * 8 + q4);
                mma_tf32(acc[j][0], acc[j][1], acc[j][2], acc[j][3],
                         a0, a1, a2, a3, wp[0], wp[4]);
            }
        }
    }

    int r0 = m0 + wm * 16 + grp;
    int r1 = r0 + 8;
    if (MODE == 0) {
        int nG = n0 + wn * 32;
        int seg = nG >> 7;
        float* dst = (seg == 0) ? g_q : (seg == 1) ? g_k : g_v;
        float sc = (seg == 0) ? QKV_SCALE : 1.0f;
        int h = (nG & 127) >> 5;
        int b0 = r0 / SEQ, nr0 = r0 - b0 * SEQ;
        int b1 = r1 / SEQ, nr1 = r1 - b1 * SEQ;
        float* d0 = dst + ((size_t)((b0 * NHEAD + h) * SEQ) + nr0) * HD + 2 * q4;
        float* d1 = dst + ((size_t)((b1 * NHEAD + h) * SEQ) + nr1) * HD + 2 * q4;
#pragma unroll
        for (int j = 0; j < 4; j++) {
            *(float2*)(d0 + j * 8) = make_float2(acc[j][0] * sc, acc[j][1] * sc);
            *(float2*)(d1 + j * 8) = make_float2(acc[j][2] * sc, acc[j][3] * sc);
        }
    } else {
        int colb = n0 + wn * 32 + 2 * q4;
        float* o0 = out + (size_t)r0 * CH + colb;
        float* o1 = out + (size_t)r1 * CH + colb;
#pragma unroll
        for (int j = 0; j < 4; j++) {
            float2 pb = *(const float2*)(bias + colb + j * 8);
            *(float2*)(o0 + j * 8) = make_float2(acc[j][0] + pb.x, acc[j][1] + pb.y);
            *(float2*)(o1 + j * 8) = make_float2(acc[j][2] + pb.x, acc[j][3] + pb.y);
        }
    }
}

// ============================================================
// Attention via mma.sync tf32: one CTA per (b,h), 8 warps,
// 2 CTAs/SM (K+V only in smem), shfl P-relayout, bias prefetch.
// ============================================================
#define ATTN_SMEM (2 * SEQ * KVSTR * 4)

__global__ void __launch_bounds__(256, 2) attn_mma(const float* __restrict__ mask) {
    extern __shared__ float sm[];
    float* Ks = sm;
    float* Vs = sm + SEQ * KVSTR;

    int g = blockIdx.x;
    int w = g >> 4;
    int r = g & 15;
    int b = (r >> 2) * NWIN + w;
    int h = r & 3;
    size_t base = ((size_t)(b * NHEAD + h) * SEQ) * HD;

    int tid = threadIdx.x;
    // ---- stage K/V (tf32-rounded) ----
    for (int s = tid; s < SEQ * 8; s += 256) {
        int row = s >> 3, c = s & 7;
        float4 k = *(const float4*)(g_k + base + (size_t)row * HD + c * 4);
        float4 v = *(const float4*)(g_v + base + (size_t)row * HD + c * 4);
        uint4 kt = make_uint4(f2tf32(k.x), f2tf32(k.y), f2tf32(k.z), f2tf32(k.w));
        uint4 vt = make_uint4(f2tf32(v.x), f2tf32(v.y), f2tf32(v.z), f2tf32(v.w));
        int o = row * KVSTR + c * 4;
        *(uint4*)(Ks + o) = kt;
        *(uint4*)(Vs + o) = vt;
    }
    __syncthreads();

    bool domask = (g_mflag[w] != 0);
    int lane = tid & 31, warp = tid >> 5;
    int grp = lane >> 2, q4 = lane & 3;
    int s1 = (lane & ~3) + (q4 >> 1);   // shfl src for cols q4
    int s2 = s1 + 2;                    // shfl src for cols q4+4

    const float* biasp = g_bias + (size_t)h * NN;
    const float* maskp = mask + (size_t)w * NN;

    for (int mt = warp; mt < MT; mt += 8) {
        int m0 = mt * 16;
        int row0 = m0 + grp;            // always < SEQ (max 391)
        int row1 = row0 + 8;
        int r1c = (row1 < SEQ) ? row1 : SEQ - 1;

        // ---- Q fragments straight from gmem ----
        const float* q0p = g_q + base + (size_t)row0 * HD;
        const float* q1p = g_q + base + (size_t)r1c * HD;
        uint32_t aq[4][4];
#pragma unroll
        for (int ks = 0; ks < 4; ks++) {
            aq[ks][0] = f2tf32(q0p[ks * 8 + q4]);
            aq[ks][1] = f2tf32(q1p[ks * 8 + q4]);
            aq[ks][2] = f2tf32(q0p[ks * 8 + q4 + 4]);
            aq[ks][3] = f2tf32(q1p[ks * 8 + q4 + 4]);
        }

        const float* b0r = biasp + (size_t)row0 * SEQ + 2 * q4;
        const float* b1r = biasp + (size_t)r1c * SEQ + 2 * q4;
        const float* m0r = maskp + (size_t)row0 * SEQ + 2 * q4;
        const float* m1r = maskp + (size_t)r1c * SEQ + 2 * q4;

        float oacc[4][4] = {};
        float rs0 = 0.0f, rs1 = 0.0f;

        // prefetch nt=0
        float2 pb0 = *(const float2*)(b0r);
        float2 pb1 = *(const float2*)(b1r);
        float2 pm0 = make_float2(0.f, 0.f), pm1 = pm0;
        if (domask) { pm0 = *(const float2*)(m0r); pm1 = *(const float2*)(m1r); }

        for (int nt = 0; nt < NT; nt++) {
            int n0 = nt * 8;
            int nn = (nt < NT - 1) ? (n0 + 8) : 0;
            float c0 = pb0.x + pm0.x, c1 = pb0.y + pm0.y;
            float c2 = pb1.x + pm1.x, c3 = pb1.y + pm1.y;
            // prefetch next tile's bias/mask
            pb0 = *(const float2*)(b0r + nn);
            pb1 = *(const float2*)(b1r + nn);
            if (domask) {
                pm0 = *(const float2*)(m0r + nn);
                pm1 = *(const float2*)(m1r + nn);
            }

            // ---- S tile: Q(16x32) @ K^T(32x8) ----
#pragma unroll
            for (int ks = 0; ks < 4; ks++) {
                const uint32_t* kp = (const uint32_t*)(Ks + (n0 + grp) * KVSTR + ks * 8 + q4);
                mma_tf32(c0, c1, c2, c3,
                         aq[ks][0], aq[ks][1], aq[ks][2], aq[ks][3],
                         kp[0], kp[4]);
            }

            // ---- unnormalized softmax ----
            float e0 = __expf(c0), e1 = __expf(c1);
            float e2 = __expf(c2), e3 = __expf(c3);
            rs0 += e0 + e1;
            rs1 += e2 + e3;

            // ---- P relayout C-frag -> A-frag via shfl ----
            uint32_t u0 = f2tf32(e0), u1 = f2tf32(e1);
            uint32_t u2 = f2tf32(e2), u3 = f2tf32(e3);
            bool oddc = (q4 & 1);
            uint32_t x0a = __shfl_sync(0xffffffffu, u0, s1);
            uint32_t x1a = __shfl_sync(0xffffffffu, u1, s1);
            uint32_t x2a = __shfl_sync(0xffffffffu, u2, s1);
            uint32_t x3a = __shfl_sync(0xffffffffu, u3, s1);
            uint32_t x0b = __shfl_sync(0xffffffffu, u0, s2);
            uint32_t x1b = __shfl_sync(0xffffffffu, u1, s2);
            uint32_t x2b = __shfl_sync(0xffffffffu, u2, s2);
            uint32_t x3b = __shfl_sync(0xffffffffu, u3, s2);
            uint32_t ap0 = oddc ? x1a : x0a;
            uint32_t ap1 = oddc ? x3a : x2a;
            uint32_t ap2 = oddc ? x1b : x0b;
            uint32_t ap3 = oddc ? x3b : x2b;

            // ---- O(16x32) += P(16x8) @ V(8x32) ----
#pragma unroll
            for (int j = 0; j < 4; j++) {
                const uint32_t* vp0 = (const uint32_t*)(Vs + (n0 + q4) * KVSTR + j * 8 + grp);
                const uint32_t* vp1 = (const uint32_t*)(Vs + (n0 + q4 + 4) * KVSTR + j * 8 + grp);
                mma_tf32(oacc[j][0], oacc[j][1], oacc[j][2], oacc[j][3],
                         ap0, ap1, ap2, ap3, vp0[0], vp1[0]);
            }
        }

        // ---- rowsum across quad, normalize, store ----
        rs0 += __shfl_xor_sync(0xffffffffu, rs0, 1);
        rs0 += __shfl_xor_sync(0xffffffffu, rs0, 2);
        rs1 += __shfl_xor_sync(0xffffffffu, rs1, 1);
        rs1 += __shfl_xor_sync(0xffffffffu, rs1, 2);
        float inv0 = __frcp_rn(rs0), inv1 = __frcp_rn(rs1);

        {
            float* op = g_ao + ((size_t)b * SEQ + row0) * CH + h * HD + 2 * q4;
#pragma unroll
            for (int j = 0; j < 4; j++)
                *(float2*)(op + j * 8) = make_float2(oacc[j][0] * inv0, oacc[j][1] * inv0);
        }
        if (row1 < SEQ) {
            float* op = g_ao + ((size_t)b * SEQ + row1) * CH + h * HD + 2 * q4;
#pragma unroll
            for (int j = 0; j < 4; j++)
                *(float2*)(op + j * 8) = make_float2(oacc[j][2] * inv1, oacc[j][3] * inv1);
        }
    }
}

// ============================================================
extern "C" void kernel_launch(void* const* d_in, const int* in_sizes, int n_in,
                              void* d_out, int out_size) {
    (void)in_sizes; (void)n_in; (void)out_size;
    const float* x          = (const float*)d_in[0];
    const float* mask       = (const float*)d_in[1];
    const float* qkv_w      = (const float*)d_in[2];
    const float* proj_w     = (const float*)d_in[3];
    const float* proj_b     = (const float*)d_in[4];
    const float* bias_table = (const float*)d_in[5];
    const int*   rel_index  = (const int*)d_in[6];
    float* out = (float*)d_out;

    cudaFuncSetAttribute(attn_mma, cudaFuncAttributeMaxDynamicSharedMemorySize, ATTN_SMEM);

    bias_gather_kernel<<<(NN + 255) / 256, 256>>>(bias_table, rel_index);
    maskflag_kernel<<<NWIN, 256>>>(mask);
    gemm_tc<0><<<dim3(MROWS / 64, 384 / 64), 256>>>(x, qkv_w, nullptr, nullptr);
    attn_mma<<<B_TOT * NHEAD, 256, ATTN_SMEM>>>(mask);
    gemm_tc<1><<<dim3(MROWS / 64, CH / 64), 256>>>(nullptr, proj_w, proj_b, out);
}